// round 2
// baseline (speedup 1.0000x reference)
#include <cuda_runtime.h>
#include <cuda_bf16.h>
#include <cstdint>

// Problem shapes (fixed by the reference)
#define B_DIM 1024
#define F_DIM 256
#define D_DIM 64

// ---------------- device-global scratch (alloc-free) ----------------
__device__ float g_trans[2][F_DIM][D_DIM];   // 128 KB
__device__ float g_qkv[3][F_DIM][D_DIM];     // 192 KB
__device__ float g_M[F_DIM][F_DIM];          // 256 KB  (cross * gate)
__device__ float g_s1[B_DIM][F_DIM];         // 1 MB
__device__ float g_c[B_DIM][F_DIM];          // 1 MB    (s0*s2)

typedef unsigned long long u64;

__device__ __forceinline__ u64 pack2(float x, float y) {
    u64 r;
    asm("mov.b64 %0, {%1, %2};" : "=l"(r) : "f"(x), "f"(y));
    return r;
}
__device__ __forceinline__ void fma2(u64& d, u64 a, u64 b, u64 c) {
    asm("fma.rn.f32x2 %0, %1, %2, %3;" : "=l"(d) : "l"(a), "l"(b), "l"(c));
}
__device__ __forceinline__ void mul2(u64& d, u64 a, u64 b) {
    asm("mul.rn.f32x2 %0, %1, %2;" : "=l"(d) : "l"(a), "l"(b));
}

// ---------------- kernel 1: trans / qkv  (5 tiny 64x64 matmuls of indicator)
// grid (F, 5), block 64.  out[n][f][e] = sum_d indicator[f,d] * W[n][d][e]
__global__ void k_transform(const float* __restrict__ ind,
                            const float* __restrict__ Wqk,
                            const float* __restrict__ Wqkv) {
    const int f = blockIdx.x;
    const int n = blockIdx.y;
    const int e = threadIdx.x;
    __shared__ float srow[D_DIM];
    srow[e] = ind[f * D_DIM + e];
    __syncthreads();
    const float* W = (n < 2) ? (Wqk + n * D_DIM * D_DIM)
                             : (Wqkv + (n - 2) * D_DIM * D_DIM);
    float acc = 0.f;
#pragma unroll
    for (int d = 0; d < D_DIM; ++d) acc = fmaf(srow[d], W[d * D_DIM + e], acc);
    if (n < 2) g_trans[n][f][e] = acc;
    else       g_qkv[n - 2][f][e] = acc;
}

// ---------------- kernel 2: M = (trans0 @ trans1^T > 0) * (qkv1 @ qkv0^T)
// grid F (=i), block 256 (=j)
__global__ void k_gate() {
    const int i = blockIdx.x;
    const int j = threadIdx.x;
    __shared__ float t0[D_DIM];
    __shared__ float q1[D_DIM];
    if (j < D_DIM)            t0[j] = g_trans[0][i][j];
    else if (j < 2 * D_DIM)   q1[j - D_DIM] = g_qkv[1][i][j - D_DIM];
    __syncthreads();
    float d1 = 0.f, d2 = 0.f;
#pragma unroll
    for (int d = 0; d < D_DIM; ++d) {
        d1 = fmaf(t0[d], g_trans[1][j][d], d1);   // gate logit (scale>0 irrelevant to sign)
        d2 = fmaf(q1[d], g_qkv[0][j][d], d2);     // cross[i,j]
    }
    g_M[i][j] = (d1 > 0.f) ? d2 : 0.f;
}

// ---------------- kernel 3: s1[b,f], c[b,f] = s0*s2
// warp per (b,f). grid 32768, block 256 (8 warps). B*F = 262144 = 32768*8.
__global__ void k_s(const float* __restrict__ feature) {
    const int warp = (blockIdx.x << 3) + (threadIdx.x >> 5);
    const int lane = threadIdx.x & 31;
    const int b = warp >> 8;        // /256
    const int f = warp & 255;

    const float2 fv = reinterpret_cast<const float2*>(
        feature + ((size_t)b * F_DIM + f) * D_DIM)[lane];
    const float2 q0 = reinterpret_cast<const float2*>(&g_qkv[0][f][0])[lane];
    const float2 q1 = reinterpret_cast<const float2*>(&g_qkv[1][f][0])[lane];
    const float2 q2 = reinterpret_cast<const float2*>(&g_qkv[2][f][0])[lane];

    float r0 = fv.x * q0.x + fv.y * q0.y;
    float r1 = fv.x * q1.x + fv.y * q1.y;
    float r2 = fv.x * q2.x + fv.y * q2.y;
#pragma unroll
    for (int off = 16; off; off >>= 1) {
        r0 += __shfl_xor_sync(0xffffffffu, r0, off);
        r1 += __shfl_xor_sync(0xffffffffu, r1, off);
        r2 += __shfl_xor_sync(0xffffffffu, r2, off);
    }
    if (lane == 0) {
        g_s1[b][f] = r1;
        g_c[b][f]  = r0 * r2;
    }
}

// ---------------- kernel 4: main GEMM
// out[b,i,d] = c[b,i] * sum_j (M[i,j]*s1[b,j]) * qkv2[j,d]
// grid (4 i-tiles, 1024 b), block 256. CTA tile 64(i) x 64(d), K=256 in 4 chunks.
// Thread micro-tile: 4 i x 4 d, packed fp32x2 FFMA over d-pairs.
#define SPAD 68
__global__ __launch_bounds__(256) void k_main(float* __restrict__ out) {
    const int b  = blockIdx.y;
    const int i0 = blockIdx.x << 6;
    const int tid = threadIdx.x;
    const int tx = tid & 15;         // d / 4
    const int ty = tid >> 4;         // i / 4

    __shared__ float sA[64][SPAD];   // (M * s1)[i][jj]
    __shared__ float sB[64][SPAD];   // qkv2[jj][d]

    u64 acc[4][2];
#pragma unroll
    for (int ii = 0; ii < 4; ++ii) { acc[ii][0] = 0ull; acc[ii][1] = 0ull; }

    const int lr = tid >> 4;         // load row base (0..15)
    const int lc = (tid & 15) << 2;  // load col (0..60 step 4)

    for (int jt = 0; jt < 4; ++jt) {
        const int j0 = jt << 6;
        const float4 s4 = *reinterpret_cast<const float4*>(&g_s1[b][j0 + lc]);
#pragma unroll
        for (int rr = 0; rr < 4; ++rr) {
            const int row = lr + (rr << 4);
            const float4 m4 = *reinterpret_cast<const float4*>(&g_M[i0 + row][j0 + lc]);
            sA[row][lc + 0] = m4.x * s4.x;
            sA[row][lc + 1] = m4.y * s4.y;
            sA[row][lc + 2] = m4.z * s4.z;
            sA[row][lc + 3] = m4.w * s4.w;
            const float4 q4 = *reinterpret_cast<const float4*>(&g_qkv[2][j0 + row][lc]);
            sB[row][lc + 0] = q4.x;
            sB[row][lc + 1] = q4.y;
            sB[row][lc + 2] = q4.z;
            sB[row][lc + 3] = q4.w;
        }
        __syncthreads();

#pragma unroll 16
        for (int jj = 0; jj < 64; ++jj) {
            const u64 b0 = *reinterpret_cast<const u64*>(&sB[jj][tx << 2]);
            const u64 b1 = *reinterpret_cast<const u64*>(&sB[jj][(tx << 2) + 2]);
#pragma unroll
            for (int ii = 0; ii < 4; ++ii) {
                const float a = sA[(ty << 2) + ii][jj];
                const u64 a2 = pack2(a, a);
                fma2(acc[ii][0], a2, b0, acc[ii][0]);
                fma2(acc[ii][1], a2, b1, acc[ii][1]);
            }
        }
        __syncthreads();
    }

    // epilogue: scale by c[b,i], vectorized 16B stores
#pragma unroll
    for (int ii = 0; ii < 4; ++ii) {
        const int i = i0 + (ty << 2) + ii;
        const float cc = g_c[b][i];
        const u64 c2 = pack2(cc, cc);
        u64 r0, r1;
        mul2(r0, acc[ii][0], c2);
        mul2(r1, acc[ii][1], c2);
        union { u64 u[2]; float4 v; } t;
        t.u[0] = r0; t.u[1] = r1;
        *reinterpret_cast<float4*>(
            out + (((size_t)b * F_DIM + i) << 6) + (tx << 2)) = t.v;
    }
}

// ---------------- launch ----------------
extern "C" void kernel_launch(void* const* d_in, const int* in_sizes, int n_in,
                              void* d_out, int out_size) {
    const float* feature   = (const float*)d_in[0];  // [1024,256,64]
    const float* indicator = (const float*)d_in[1];  // [256,64]
    const float* W_qk      = (const float*)d_in[2];  // [2,64,64]
    const float* W_qkv     = (const float*)d_in[3];  // [3,64,64]
    float* out = (float*)d_out;                      // [1024,256,64]

    k_transform<<<dim3(F_DIM, 5), D_DIM>>>(indicator, W_qk, W_qkv);
    k_gate<<<F_DIM, F_DIM>>>();
    k_s<<<(B_DIM * F_DIM) / 8, 256>>>(feature);
    k_main<<<dim3(F_DIM / 64, B_DIM), 256>>>(out);
}

// round 4
// speedup vs baseline: 1.5248x; 1.5248x over previous
#include <cuda_runtime.h>
#include <cuda_bf16.h>
#include <cstdint>

// Problem shapes (fixed by the reference)
#define B_DIM 1024
#define F_DIM 256
#define D_DIM 64
#define N_TOT (F_DIM * D_DIM)   // 16384

// ---------------- device-global scratch (alloc-free) ----------------
__device__ float g_trans[2][F_DIM][D_DIM];            // 128 KB
__device__ float g_qkv[3][F_DIM][D_DIM];              // 192 KB
__device__ float g_M[F_DIM][F_DIM];                   // 256 KB (cross * gate)
__device__ float g_c[B_DIM][F_DIM];                   // 1 MB   (s0*s2)
__device__ __nv_bfloat16 g_Ahi[B_DIM * F_DIM];        // 512 KB  s1 hi
__device__ __nv_bfloat16 g_Alo[B_DIM * F_DIM];        // 512 KB  s1 lo
__device__ __nv_bfloat16 g_Phi[(size_t)N_TOT * F_DIM];// 8 MB    P hi
__device__ __nv_bfloat16 g_Plo[(size_t)N_TOT * F_DIM];// 8 MB    P lo

// ---------------- PTX helpers (plain sm_103-safe: no tcgen05) -------------
__device__ __forceinline__ uint32_t smem_to_u32(const void* p) {
    uint32_t a;
    asm("{ .reg .u64 t; cvta.to.shared.u64 t, %1; cvt.u32.u64 %0, t; }"
        : "=r"(a) : "l"(p));
    return a;
}

#define CP_ASYNC16(dst, src) \
    asm volatile("cp.async.cg.shared.global [%0], [%1], 16;" \
                 :: "r"(dst), "l"(src))
#define CP_COMMIT() asm volatile("cp.async.commit_group;" ::: "memory")
#define CP_WAIT(n)  asm volatile("cp.async.wait_group %0;" :: "n"(n) : "memory")

#define LDSM4(r, addr) \
    asm volatile("ldmatrix.sync.aligned.m8n8.x4.shared.b16 {%0,%1,%2,%3}, [%4];" \
                 : "=r"((r)[0]), "=r"((r)[1]), "=r"((r)[2]), "=r"((r)[3]) \
                 : "r"(addr))

#define MMA16816(d, a, br0, br1) \
    asm volatile("mma.sync.aligned.m16n8k16.row.col.f32.bf16.bf16.f32 " \
                 "{%0,%1,%2,%3}, {%4,%5,%6,%7}, {%8,%9}, {%0,%1,%2,%3};" \
                 : "+f"((d)[0]), "+f"((d)[1]), "+f"((d)[2]), "+f"((d)[3]) \
                 : "r"((a)[0]), "r"((a)[1]), "r"((a)[2]), "r"((a)[3]), \
                   "r"(br0), "r"(br1))

// ---------------- kernel 1: trans / qkv  (5 tiny 64x64 matmuls)
__global__ void k_transform(const float* __restrict__ ind,
                            const float* __restrict__ Wqk,
                            const float* __restrict__ Wqkv) {
    const int f = blockIdx.x;
    const int n = blockIdx.y;
    const int e = threadIdx.x;
    __shared__ float srow[D_DIM];
    srow[e] = ind[f * D_DIM + e];
    __syncthreads();
    const float* W = (n < 2) ? (Wqk + n * D_DIM * D_DIM)
                             : (Wqkv + (n - 2) * D_DIM * D_DIM);
    float acc = 0.f;
#pragma unroll
    for (int d = 0; d < D_DIM; ++d) acc = fmaf(srow[d], W[d * D_DIM + e], acc);
    if (n < 2) g_trans[n][f][e] = acc;
    else       g_qkv[n - 2][f][e] = acc;
}

// ---------------- kernel 2: M = (trans0 @ trans1^T > 0) * (qkv1 @ qkv0^T)
__global__ void k_gate() {
    const int i = blockIdx.x;
    const int j = threadIdx.x;
    __shared__ float t0[D_DIM];
    __shared__ float q1[D_DIM];
    if (j < D_DIM)            t0[j] = g_trans[0][i][j];
    else if (j < 2 * D_DIM)   q1[j - D_DIM] = g_qkv[1][i][j - D_DIM];
    __syncthreads();
    float d1 = 0.f, d2 = 0.f;
#pragma unroll
    for (int d = 0; d < D_DIM; ++d) {
        d1 = fmaf(t0[d], g_trans[1][j][d], d1);
        d2 = fmaf(q1[d], g_qkv[0][j][d], d2);
    }
    g_M[i][j] = (d1 > 0.f) ? d2 : 0.f;
}

// ---------------- kernel 3: s1 (split bf16 hi/lo) and c = s0*s2
__global__ void k_s(const float* __restrict__ feature) {
    const int warp = (blockIdx.x << 3) + (threadIdx.x >> 5);
    const int lane = threadIdx.x & 31;
    const int b = warp >> 8;
    const int f = warp & 255;

    const float2 fv = reinterpret_cast<const float2*>(
        feature + ((size_t)b * F_DIM + f) * D_DIM)[lane];
    const float2 q0 = reinterpret_cast<const float2*>(&g_qkv[0][f][0])[lane];
    const float2 q1 = reinterpret_cast<const float2*>(&g_qkv[1][f][0])[lane];
    const float2 q2 = reinterpret_cast<const float2*>(&g_qkv[2][f][0])[lane];

    float r0 = fv.x * q0.x + fv.y * q0.y;
    float r1 = fv.x * q1.x + fv.y * q1.y;
    float r2 = fv.x * q2.x + fv.y * q2.y;
#pragma unroll
    for (int off = 16; off; off >>= 1) {
        r0 += __shfl_xor_sync(0xffffffffu, r0, off);
        r1 += __shfl_xor_sync(0xffffffffu, r1, off);
        r2 += __shfl_xor_sync(0xffffffffu, r2, off);
    }
    if (lane == 0) {
        g_c[b][f] = r0 * r2;
        __nv_bfloat16 hi = __float2bfloat16_rn(r1);
        g_Ahi[b * F_DIM + f] = hi;
        g_Alo[b * F_DIM + f] = __float2bfloat16_rn(r1 - __bfloat162float(hi));
    }
}

// ---------------- kernel 4: P[(i,d), j] = M[i,j] * qkv2[j,d], split hi/lo
// grid (256 i, 8 dg), block 256 (j). Each block covers 8 d values.
__global__ void k_P() {
    const int i  = blockIdx.x;
    const int d0 = blockIdx.y << 3;
    const int j  = threadIdx.x;
    const float m = g_M[i][j];
#pragma unroll
    for (int dd = 0; dd < 8; ++dd) {
        const int d = d0 + dd;
        const float v = m * g_qkv[2][j][d];
        const __nv_bfloat16 hi = __float2bfloat16_rn(v);
        const float lo = v - __bfloat162float(hi);
        const size_t n = (size_t)((i << 6) + d) * F_DIM + j;
        g_Phi[n] = hi;
        g_Plo[n] = __float2bfloat16_rn(lo);
    }
}

// ---------------- kernel 5: HMMA GEMM  out[b,n] = c[b,n>>6] * (s1 @ P^T)
// CTA tile M=128(b) x N=128(n), K=256 in 8 chunks of 32, cp.async double buffer.
// 8 warps in 4(M) x 2(N); warp tile 32 x 64; mma.m16n8k16 bf16->f32.
// Compensated: acc += Ahi*Bhi + Ahi*Blo + Alo*Bhi.
static constexpr int SROW_B   = 80;          // bytes per smem row (32 bf16 + 16B pad)
static constexpr int ARR_B    = 128 * SROW_B;      // 10240 per array
static constexpr int STAGE_B  = 4 * ARR_B;         // 40960 per stage (Ahi,Alo,Bhi,Blo)
static constexpr int SMEM_SZ  = 2 * STAGE_B;       // 81920

__global__ __launch_bounds__(256) void k_mma(float* __restrict__ out) {
    extern __shared__ char smem[];
    const uint32_t sb = smem_to_u32(smem);
    const int tid  = threadIdx.x;
    const int wid  = tid >> 5;
    const int lane = tid & 31;
    const int n0 = blockIdx.x << 7;    // 128 n-tiles
    const int b0 = blockIdx.y << 7;    // 8 b-tiles

    const int warp_m = (wid >> 1) * 32;   // 0,32,64,96
    const int warp_n = (wid & 1) * 64;    // 0,64

    // ldmatrix lane address component: row (lane&15), 16B col block (lane>>4)
    const uint32_t laneRC = (uint32_t)((lane & 15) * SROW_B + (lane >> 4) * 16);

    float acc[2][8][4];
#pragma unroll
    for (int mt = 0; mt < 2; ++mt)
#pragma unroll
        for (int nt = 0; nt < 8; ++nt)
#pragma unroll
            for (int e = 0; e < 4; ++e) acc[mt][nt][e] = 0.f;

    // ---- stage loader: 2048 x 16B cp.async (A hi/lo 128x32, B hi/lo 128x32)
    auto load_stage = [&](int st, int ch) {
        const int j0 = ch << 5;
        const uint32_t dst0 = sb + st * STAGE_B;
#pragma unroll
        for (int it = 0; it < 8; ++it) {
            const int e = tid + it * 256;      // 0..2047
            const int arr = e >> 9;            // 0..3
            const int r   = (e >> 2) & 127;
            const int c   = e & 3;
            const uint32_t dst = dst0 + arr * ARR_B + r * SROW_B + c * 16;
            const __nv_bfloat16* src;
            if (arr == 0)      src = g_Ahi + (size_t)(b0 + r) * F_DIM + j0 + c * 8;
            else if (arr == 1) src = g_Alo + (size_t)(b0 + r) * F_DIM + j0 + c * 8;
            else if (arr == 2) src = g_Phi + (size_t)(n0 + r) * F_DIM + j0 + c * 8;
            else               src = g_Plo + (size_t)(n0 + r) * F_DIM + j0 + c * 8;
            CP_ASYNC16(dst, src);
        }
    };

    load_stage(0, 0);
    CP_COMMIT();

    for (int ch = 0; ch < 8; ++ch) {
        const int st = ch & 1;
        if (ch + 1 < 8) {
            load_stage(st ^ 1, ch + 1);
            CP_COMMIT();
            CP_WAIT(1);
        } else {
            CP_WAIT(0);
        }
        __syncthreads();

        const uint32_t aHi = sb + st * STAGE_B + (uint32_t)warp_m * SROW_B + laneRC;
        const uint32_t aLo = aHi + ARR_B;
        const uint32_t bHi = sb + st * STAGE_B + 2 * ARR_B + (uint32_t)warp_n * SROW_B + laneRC;
        const uint32_t bLo = bHi + ARR_B;

#pragma unroll
        for (int ks = 0; ks < 2; ++ks) {
            uint32_t ah[2][4], al[2][4], bh[4][4], bl[4][4];
#pragma unroll
            for (int mt = 0; mt < 2; ++mt) {
                LDSM4(ah[mt], aHi + mt * 16 * SROW_B + ks * 32);
                LDSM4(al[mt], aLo + mt * 16 * SROW_B + ks * 32);
            }
#pragma unroll
            for (int p = 0; p < 4; ++p) {
                LDSM4(bh[p], bHi + p * 16 * SROW_B + ks * 32);
                LDSM4(bl[p], bLo + p * 16 * SROW_B + ks * 32);
            }
#pragma unroll
            for (int mt = 0; mt < 2; ++mt)
#pragma unroll
                for (int p = 0; p < 4; ++p)
#pragma unroll
                    for (int s = 0; s < 2; ++s) {
                        const int nt = p * 2 + s;
                        MMA16816(acc[mt][nt], ah[mt], bh[p][s], bh[p][s + 2]);
                        MMA16816(acc[mt][nt], ah[mt], bl[p][s], bl[p][s + 2]);
                        MMA16816(acc[mt][nt], al[mt], bh[p][s], bh[p][s + 2]);
                    }
        }
        __syncthreads();
    }

    // ---- epilogue: scale by c[b,i] (i constant over the warp's 64 n-cols)
    const int i_idx = (n0 + warp_n) >> 6;
#pragma unroll
    for (int mt = 0; mt < 2; ++mt) {
        const int r0 = b0 + warp_m + mt * 16 + (lane >> 2);
        const int r1 = r0 + 8;
        const float cc0 = g_c[r0][i_idx];
        const float cc1 = g_c[r1][i_idx];
#pragma unroll
        for (int nt = 0; nt < 8; ++nt) {
            const int col = n0 + warp_n + nt * 8 + (lane & 3) * 2;
            float2 v0 = { acc[mt][nt][0] * cc0, acc[mt][nt][1] * cc0 };
            float2 v1 = { acc[mt][nt][2] * cc1, acc[mt][nt][3] * cc1 };
            *reinterpret_cast<float2*>(out + (size_t)r0 * N_TOT + col) = v0;
            *reinterpret_cast<float2*>(out + (size_t)r1 * N_TOT + col) = v1;
        }
    }
}

// ---------------- launch ----------------
extern "C" void kernel_launch(void* const* d_in, const int* in_sizes, int n_in,
                              void* d_out, int out_size) {
    const float* feature   = (const float*)d_in[0];  // [1024,256,64]
    const float* indicator = (const float*)d_in[1];  // [256,64]
    const float* W_qk      = (const float*)d_in[2];  // [2,64,64]
    const float* W_qkv     = (const float*)d_in[3];  // [3,64,64]
    float* out = (float*)d_out;                      // [1024,256,64]

    cudaFuncSetAttribute((const void*)k_mma,
                         cudaFuncAttributeMaxDynamicSharedMemorySize, SMEM_SZ);

    k_transform<<<dim3(F_DIM, 5), D_DIM>>>(indicator, W_qk, W_qkv);
    k_gate<<<F_DIM, F_DIM>>>();
    k_s<<<(B_DIM * F_DIM) / 8, 256>>>(feature);
    k_P<<<dim3(F_DIM, 8), F_DIM>>>();
    k_mma<<<dim3(N_TOT / 128, B_DIM / 128), 256, SMEM_SZ>>>(out);
}

// round 6
// speedup vs baseline: 1.5909x; 1.0433x over previous
#include <cuda_runtime.h>
#include <cuda_bf16.h>
#include <cstdint>

// Problem shapes (fixed by the reference)
#define B_DIM 1024
#define F_DIM 256
#define D_DIM 64
#define N_TOT (F_DIM * D_DIM)   // 16384

// ---------------- device-global scratch (alloc-free) ----------------
__device__ float g_trans[2][F_DIM][D_DIM];            // 128 KB
__device__ float g_qkv[3][F_DIM][D_DIM];              // 192 KB
__device__ float g_qkv2T[D_DIM][F_DIM];               // 64 KB (qkv[2] transposed)
__device__ float g_c[B_DIM][F_DIM];                   // 1 MB   (s0*s2)
__device__ __nv_bfloat16 g_Ahi[B_DIM * F_DIM];        // 512 KB  s1 hi
__device__ __nv_bfloat16 g_Alo[B_DIM * F_DIM];        // 512 KB  s1 lo
__device__ __nv_bfloat16 g_Phi[(size_t)N_TOT * F_DIM];// 8 MB    P hi
__device__ __nv_bfloat16 g_Plo[(size_t)N_TOT * F_DIM];// 8 MB    P lo

// ---------------- PTX helpers (plain sm_103-safe: no tcgen05) -------------
__device__ __forceinline__ uint32_t smem_to_u32(const void* p) {
    uint32_t a;
    asm("{ .reg .u64 t; cvta.to.shared.u64 t, %1; cvt.u32.u64 %0, t; }"
        : "=r"(a) : "l"(p));
    return a;
}

#define CP_ASYNC16(dst, src) \
    asm volatile("cp.async.cg.shared.global [%0], [%1], 16;" \
                 :: "r"(dst), "l"(src))
#define CP_COMMIT() asm volatile("cp.async.commit_group;" ::: "memory")
#define CP_WAIT(n)  asm volatile("cp.async.wait_group %0;" :: "n"(n) : "memory")

#define LDSM4(r, addr) \
    asm volatile("ldmatrix.sync.aligned.m8n8.x4.shared.b16 {%0,%1,%2,%3}, [%4];" \
                 : "=r"((r)[0]), "=r"((r)[1]), "=r"((r)[2]), "=r"((r)[3]) \
                 : "r"(addr))

#define MMA16816(d, a, br0, br1) \
    asm volatile("mma.sync.aligned.m16n8k16.row.col.f32.bf16.bf16.f32 " \
                 "{%0,%1,%2,%3}, {%4,%5,%6,%7}, {%8,%9}, {%0,%1,%2,%3};" \
                 : "+f"((d)[0]), "+f"((d)[1]), "+f"((d)[2]), "+f"((d)[3]) \
                 : "r"((a)[0]), "r"((a)[1]), "r"((a)[2]), "r"((a)[3]), \
                   "r"(br0), "r"(br1))

// ---------------- kernel 1: trans / qkv  (5 tiny 64x64 matmuls)
__global__ void k_transform(const float* __restrict__ ind,
                            const float* __restrict__ Wqk,
                            const float* __restrict__ Wqkv) {
    const int f = blockIdx.x;
    const int n = blockIdx.y;
    const int e = threadIdx.x;
    __shared__ float srow[D_DIM];
    srow[e] = ind[f * D_DIM + e];
    __syncthreads();
    const float* W = (n < 2) ? (Wqk + n * D_DIM * D_DIM)
                             : (Wqkv + (n - 2) * D_DIM * D_DIM);
    float acc = 0.f;
#pragma unroll
    for (int d = 0; d < D_DIM; ++d) acc = fmaf(srow[d], W[d * D_DIM + e], acc);
    if (n < 2) g_trans[n][f][e] = acc;
    else {
        g_qkv[n - 2][f][e] = acc;
        if (n == 4) g_qkv2T[e][f] = acc;   // transposed copy for k_gateP
    }
}

// ---------------- kernel 2 (fused gate + P):
// M[i,j] = (trans0[i].trans1[j] > 0) * (qkv1[i].qkv0[j])
// P[(i,d), j] = M[i,j] * qkv2[j,d], split bf16 hi/lo. grid 256(i), block 256(j).
__global__ void k_gateP() {
    const int i = blockIdx.x;
    const int j = threadIdx.x;
    __shared__ float t0[D_DIM];
    __shared__ float q1[D_DIM];
    if (j < D_DIM)            t0[j] = g_trans[0][i][j];
    else if (j < 2 * D_DIM)   q1[j - D_DIM] = g_qkv[1][i][j - D_DIM];
    __syncthreads();
    float d1 = 0.f, d2 = 0.f;
#pragma unroll
    for (int d = 0; d < D_DIM; ++d) {
        d1 = fmaf(t0[d], g_trans[1][j][d], d1);
        d2 = fmaf(q1[d], g_qkv[0][j][d], d2);
    }
    const float m = (d1 > 0.f) ? d2 : 0.f;
    const size_t base = ((size_t)i << 6) * F_DIM + j;
#pragma unroll 8
    for (int d = 0; d < D_DIM; ++d) {
        const float v = m * g_qkv2T[d][j];                  // coalesced read
        const __nv_bfloat16 hi = __float2bfloat16_rn(v);
        const float lo = v - __bfloat162float(hi);
        g_Phi[base + (size_t)d * F_DIM] = hi;               // coalesced write
        g_Plo[base + (size_t)d * F_DIM] = __float2bfloat16_rn(lo);
    }
}

// ---------------- kernel 3: s1 (split bf16 hi/lo) and c = s0*s2
__global__ void k_s(const float* __restrict__ feature) {
    const int warp = (blockIdx.x << 3) + (threadIdx.x >> 5);
    const int lane = threadIdx.x & 31;
    const int b = warp >> 8;
    const int f = warp & 255;

    const float2 fv = reinterpret_cast<const float2*>(
        feature + ((size_t)b * F_DIM + f) * D_DIM)[lane];
    const float2 q0 = reinterpret_cast<const float2*>(&g_qkv[0][f][0])[lane];
    const float2 q1 = reinterpret_cast<const float2*>(&g_qkv[1][f][0])[lane];
    const float2 q2 = reinterpret_cast<const float2*>(&g_qkv[2][f][0])[lane];

    float r0 = fv.x * q0.x + fv.y * q0.y;
    float r1 = fv.x * q1.x + fv.y * q1.y;
    float r2 = fv.x * q2.x + fv.y * q2.y;
#pragma unroll
    for (int off = 16; off; off >>= 1) {
        r0 += __shfl_xor_sync(0xffffffffu, r0, off);
        r1 += __shfl_xor_sync(0xffffffffu, r1, off);
        r2 += __shfl_xor_sync(0xffffffffu, r2, off);
    }
    if (lane == 0) {
        g_c[b][f] = r0 * r2;
        __nv_bfloat16 hi = __float2bfloat16_rn(r1);
        g_Ahi[b * F_DIM + f] = hi;
        g_Alo[b * F_DIM + f] = __float2bfloat16_rn(r1 - __bfloat162float(hi));
    }
}

// ---------------- kernel 4: HMMA GEMM  out[b,n] = c[b,n>>6] * (s1 @ P^T)
// CTA tile M=128(b) x N=128(n), K=256 in 8 chunks of 32, cp.async double buffer.
// 8 warps in 4(M) x 2(N); warp tile 32 x 64; mma.m16n8k16 bf16->f32.
// Compensated: acc += Ahi*Bhi + Ahi*Blo + Alo*Bhi.
static constexpr int SROW_B   = 80;                // bytes per smem row (32 bf16 + 16B pad)
static constexpr int ARR_B    = 128 * SROW_B;      // 10240 per array
static constexpr int STAGE_B  = 4 * ARR_B;         // 40960 per stage (Ahi,Alo,Bhi,Blo)
static constexpr int SMEM_SZ  = 2 * STAGE_B;       // 81920

__global__ __launch_bounds__(256, 2) void k_mma(float* __restrict__ out) {
    extern __shared__ char smem[];
    const uint32_t sb = smem_to_u32(smem);
    const int tid  = threadIdx.x;
    const int wid  = tid >> 5;
    const int lane = tid & 31;
    const int n0 = blockIdx.x << 7;    // 128 n-tiles
    const int b0 = blockIdx.y << 7;    // 8 b-tiles

    const int warp_m = (wid >> 1) * 32;   // 0,32,64,96
    const int warp_n = (wid & 1) * 64;    // 0,64

    // ldmatrix lane address component: row (lane&15), 16B col block (lane>>4)
    const uint32_t laneRC = (uint32_t)((lane & 15) * SROW_B + (lane >> 4) * 16);

    float acc[2][8][4];
#pragma unroll
    for (int mt = 0; mt < 2; ++mt)
#pragma unroll
        for (int nt = 0; nt < 8; ++nt)
#pragma unroll
            for (int e = 0; e < 4; ++e) acc[mt][nt][e] = 0.f;

    // ---- stage loader: 2048 x 16B cp.async (A hi/lo 128x32, B hi/lo 128x32)
    auto load_stage = [&](int st, int ch) {
        const int j0 = ch << 5;
        const uint32_t dst0 = sb + st * STAGE_B;
#pragma unroll
        for (int it = 0; it < 8; ++it) {
            const int e = tid + it * 256;      // 0..2047
            const int arr = e >> 9;            // 0..3
            const int r   = (e >> 2) & 127;
            const int c   = e & 3;
            const uint32_t dst = dst0 + arr * ARR_B + r * SROW_B + c * 16;
            const __nv_bfloat16* src;
            if (arr == 0)      src = g_Ahi + (size_t)(b0 + r) * F_DIM + j0 + c * 8;
            else if (arr == 1) src = g_Alo + (size_t)(b0 + r) * F_DIM + j0 + c * 8;
            else if (arr == 2) src = g_Phi + (size_t)(n0 + r) * F_DIM + j0 + c * 8;
            else               src = g_Plo + (size_t)(n0 + r) * F_DIM + j0 + c * 8;
            CP_ASYNC16(dst, src);
        }
    };

    load_stage(0, 0);
    CP_COMMIT();

    for (int ch = 0; ch < 8; ++ch) {
        const int st = ch & 1;
        if (ch + 1 < 8) {
            load_stage(st ^ 1, ch + 1);
            CP_COMMIT();
            CP_WAIT(1);
        } else {
            CP_WAIT(0);
        }
        __syncthreads();

        const uint32_t aHi = sb + st * STAGE_B + (uint32_t)warp_m * SROW_B + laneRC;
        const uint32_t aLo = aHi + ARR_B;
        const uint32_t bHi = sb + st * STAGE_B + 2 * ARR_B + (uint32_t)warp_n * SROW_B + laneRC;
        const uint32_t bLo = bHi + ARR_B;

#pragma unroll
        for (int ks = 0; ks < 2; ++ks) {
            uint32_t ah[2][4], al[2][4];
#pragma unroll
            for (int mt = 0; mt < 2; ++mt) {
                LDSM4(ah[mt], aHi + mt * 16 * SROW_B + ks * 32);
                LDSM4(al[mt], aLo + mt * 16 * SROW_B + ks * 32);
            }
            // process B in two p-groups of 2 to cap live registers (<=128/thread)
#pragma unroll
            for (int pg = 0; pg < 2; ++pg) {
                uint32_t bh[2][4], bl[2][4];
#pragma unroll
                for (int pi = 0; pi < 2; ++pi) {
                    const int p = pg * 2 + pi;
                    LDSM4(bh[pi], bHi + p * 16 * SROW_B + ks * 32);
                    LDSM4(bl[pi], bLo + p * 16 * SROW_B + ks * 32);
                }
#pragma unroll
                for (int mt = 0; mt < 2; ++mt)
#pragma unroll
                    for (int pi = 0; pi < 2; ++pi)
#pragma unroll
                        for (int s = 0; s < 2; ++s) {
                            const int nt = (pg * 2 + pi) * 2 + s;
                            MMA16816(acc[mt][nt], ah[mt], bh[pi][s], bh[pi][s + 2]);
                            MMA16816(acc[mt][nt], ah[mt], bl[pi][s], bl[pi][s + 2]);
                            MMA16816(acc[mt][nt], al[mt], bh[pi][s], bh[pi][s + 2]);
                        }
            }
        }
        __syncthreads();
    }

    // ---- epilogue: scale by c[b,i] (i constant over the warp's 64 n-cols)
    const int i_idx = (n0 + warp_n) >> 6;
#pragma unroll
    for (int mt = 0; mt < 2; ++mt) {
        const int r0 = b0 + warp_m + mt * 16 + (lane >> 2);
        const int r1 = r0 + 8;
        const float cc0 = g_c[r0][i_idx];
        const float cc1 = g_c[r1][i_idx];
#pragma unroll
        for (int nt = 0; nt < 8; ++nt) {
            const int col = n0 + warp_n + nt * 8 + (lane & 3) * 2;
            float2 v0 = { acc[mt][nt][0] * cc0, acc[mt][nt][1] * cc0 };
            float2 v1 = { acc[mt][nt][2] * cc1, acc[mt][nt][3] * cc1 };
            *reinterpret_cast<float2*>(out + (size_t)r0 * N_TOT + col) = v0;
            *reinterpret_cast<float2*>(out + (size_t)r1 * N_TOT + col) = v1;
        }
    }
}

// ---------------- launch ----------------
extern "C" void kernel_launch(void* const* d_in, const int* in_sizes, int n_in,
                              void* d_out, int out_size) {
    const float* feature   = (const float*)d_in[0];  // [1024,256,64]
    const float* indicator = (const float*)d_in[1];  // [256,64]
    const float* W_qk      = (const float*)d_in[2];  // [2,64,64]
    const float* W_qkv     = (const float*)d_in[3];  // [3,64,64]
    float* out = (float*)d_out;                      // [1024,256,64]

    cudaFuncSetAttribute((const void*)k_mma,
                         cudaFuncAttributeMaxDynamicSharedMemorySize, SMEM_SZ);

    // k_mma is launch #4 — ncu captures launch #4 (observed rounds 2 & 4)
    k_transform<<<dim3(F_DIM, 5), D_DIM>>>(indicator, W_qk, W_qkv);
    k_gateP<<<F_DIM, F_DIM>>>();
    k_s<<<(B_DIM * F_DIM) / 8, 256>>>(feature);
    k_mma<<<dim3(N_TOT / 128, B_DIM / 128), 256, SMEM_SZ>>>(out);
}